// round 2
// baseline (speedup 1.0000x reference)
#include <cuda_runtime.h>
#include <cstdint>

#define NROWS 8192
#define DIM 128

// Static scratch (allocation-free per harness rules)
__device__ float g_dis[NROWS];                        // rsqrt(rowsum(A)+1)
__device__ float g_z[(size_t)NROWS * DIM];            // G[j][n] = dis_j * (X W^T)[j][n], tf32-rounded
__device__ float g_part[2][(size_t)NROWS * DIM];      // split-K partials of A @ G

static __device__ __forceinline__ uint32_t s2u(const void* p) {
    uint32_t a;
    asm("{ .reg .u64 t; cvta.to.shared.u64 t, %1; cvt.u32.u64 %0, t; }" : "=r"(a) : "l"(p));
    return a;
}

// ===================== kernel 1: row sums -> dis =====================
__global__ void __launch_bounds__(256) rowsum_kernel(const float4* __restrict__ A4) {
    int row = blockIdx.x;
    const float4* r = A4 + (size_t)row * (NROWS / 4);
    float s = 0.f;
    #pragma unroll
    for (int p = 0; p < 8; p++) {
        float4 v = r[threadIdx.x + p * 256];
        s += (v.x + v.y) + (v.z + v.w);
    }
    #pragma unroll
    for (int o = 16; o; o >>= 1) s += __shfl_xor_sync(0xffffffffu, s, o);
    __shared__ float ws[8];
    if ((threadIdx.x & 31) == 0) ws[threadIdx.x >> 5] = s;
    __syncthreads();
    if (threadIdx.x < 8) {
        float t = ws[threadIdx.x];
        #pragma unroll
        for (int o = 4; o; o >>= 1) t += __shfl_xor_sync(0xffu, t, o);
        if (threadIdx.x == 0) g_dis[row] = rsqrtf(t + 1.0f);
    }
}

// ===================== kernel 2: G[j][n] = dis_j * (X W^T), tf32-rounded, row-major =====================
__global__ void __launch_bounds__(256) z_kernel(const float* __restrict__ X,
                                                const float* __restrict__ W) {
    __shared__ float4 Xs4[32 * 32];  // 32 rows x 128 floats
    int tid = threadIdx.x;
    int j0 = blockIdx.x * 32;
    const float4* Xg = reinterpret_cast<const float4*>(X) + (size_t)j0 * 32;
    for (int i = tid; i < 1024; i += 256) Xs4[i] = Xg[i];
    __syncthreads();

    int n = tid & 127, half = tid >> 7;
    float acc[16];
    #pragma unroll
    for (int jj = 0; jj < 16; jj++) acc[jj] = 0.f;

    const float4* Wr = reinterpret_cast<const float4*>(W) + (size_t)n * 32;
    #pragma unroll 4
    for (int c4 = 0; c4 < 32; c4++) {
        float4 w = __ldg(Wr + c4);
        #pragma unroll
        for (int jj = 0; jj < 16; jj++) {
            float4 x = Xs4[(half * 16 + jj) * 32 + c4];
            acc[jj] += x.x * w.x + x.y * w.y + x.z * w.z + x.w * w.w;
        }
    }
    #pragma unroll
    for (int jj = 0; jj < 16; jj++) {
        int j = j0 + half * 16 + jj;
        float z = g_dis[j] * acc[jj];
        unsigned zb;
        asm("cvt.rna.tf32.f32 %0, %1;" : "=r"(zb) : "f"(z));
        g_z[(size_t)j * DIM + n] = __uint_as_float(zb);
    }
}

// ===================== kernel 3: split-K tf32 mma.sync GEMM: g_part[kh] = A[:, kh-half] @ G[kh-half, :] =====================
#define BK 32
#define STG 4
#define ASTR 36                      // padded floats per A-tile row (conflict-free frags)
#define BSTR 136                     // padded floats per B-tile row
#define ASTG (128 * ASTR)            // 4608 floats per A stage
#define BSTG (BK * BSTR)             // 4352 floats per B stage
#define SMEM_FLOATS (STG * (ASTG + BSTG))
#define SMEM_BYTES (SMEM_FLOATS * 4) // 143360 B

static __device__ __forceinline__ void mma_tf32(float* c, const uint32_t* a, const uint32_t* b) {
    asm volatile(
        "mma.sync.aligned.m16n8k8.row.col.f32.tf32.tf32.f32 "
        "{%0,%1,%2,%3}, {%4,%5,%6,%7}, {%8,%9}, {%0,%1,%2,%3};"
        : "+f"(c[0]), "+f"(c[1]), "+f"(c[2]), "+f"(c[3])
        : "r"(a[0]), "r"(a[1]), "r"(a[2]), "r"(a[3]), "r"(b[0]), "r"(b[1]));
}

__global__ void __launch_bounds__(128) gemm_kernel(const float* __restrict__ A) {
    extern __shared__ float sm[];
    float* sA = sm;                  // [STG][ASTG]
    float* sB = sm + STG * ASTG;     // [STG][BSTG]
    const float* Bm = g_z;

    int tid = threadIdx.x, wid = tid >> 5, lane = tid & 31;
    int gid = lane >> 2, tig = lane & 3;
    const int m0 = blockIdx.x * 128;
    const int kbase = blockIdx.y * (NROWS / 2);

    float acc[4][8][4];
    #pragma unroll
    for (int mf = 0; mf < 4; mf++)
        #pragma unroll
        for (int nf = 0; nf < 8; nf++)
            #pragma unroll
            for (int q = 0; q < 4; q++) acc[mf][nf][q] = 0.f;

    const int wm0 = (wid >> 1) * 64, wn0 = (wid & 1) * 64;

    // async-copy one stage (A 128xBK, B BKx128), 8+8 float4 per thread
    auto issue = [&](int stage, int buf) {
        int kk = kbase + stage * BK;
        #pragma unroll
        for (int it = 0; it < 8; it++) {
            int idx = it * 128 + tid;
            int r = idx >> 3, c4 = idx & 7;
            const float* gp = A + (size_t)(m0 + r) * NROWS + kk + c4 * 4;
            uint32_t sa = s2u(sA + buf * ASTG + r * ASTR + c4 * 4);
            asm volatile("cp.async.cg.shared.global [%0], [%1], 16;" :: "r"(sa), "l"(gp));
        }
        #pragma unroll
        for (int it = 0; it < 8; it++) {
            int idx = it * 128 + tid;
            int r = idx >> 5, c4 = idx & 31;
            const float* gp = Bm + (size_t)(kk + r) * DIM + c4 * 4;
            uint32_t sb = s2u(sB + buf * BSTG + r * BSTR + c4 * 4);
            asm volatile("cp.async.cg.shared.global [%0], [%1], 16;" :: "r"(sb), "l"(gp));
        }
        asm volatile("cp.async.commit_group;");
    };

    #pragma unroll
    for (int s = 0; s < STG - 1; s++) issue(s, s);

    const int NS = (NROWS / 2) / BK;  // 128 stages
    for (int i = 0; i < NS; i++) {
        asm volatile("cp.async.wait_group %0;" :: "n"(STG - 2));
        __syncthreads();
        if (i + STG - 1 < NS) issue(i + STG - 1, (i + STG - 1) & (STG - 1));

        const float* a_s = sA + (i & (STG - 1)) * ASTG;
        const float* b_s = sB + (i & (STG - 1)) * BSTG;

        #pragma unroll
        for (int ks = 0; ks < BK / 8; ks++) {
            int k0 = ks * 8;
            uint32_t ar[4][4], br[8][2];
            #pragma unroll
            for (int mf = 0; mf < 4; mf++) {
                const float* p = a_s + (wm0 + mf * 16 + gid) * ASTR + k0 + tig;
                ar[mf][0] = __float_as_uint(p[0]);
                ar[mf][1] = __float_as_uint(p[8 * ASTR]);
                ar[mf][2] = __float_as_uint(p[4]);
                ar[mf][3] = __float_as_uint(p[8 * ASTR + 4]);
            }
            #pragma unroll
            for (int nf = 0; nf < 8; nf++) {
                const float* p = b_s + (k0 + tig) * BSTR + wn0 + nf * 8 + gid;
                br[nf][0] = __float_as_uint(p[0]);
                br[nf][1] = __float_as_uint(p[4 * BSTR]);
            }
            #pragma unroll
            for (int mf = 0; mf < 4; mf++)
                #pragma unroll
                for (int nf = 0; nf < 8; nf++)
                    mma_tf32(acc[mf][nf], ar[mf], br[nf]);
        }
    }

    // write split-K partials
    float* P = g_part[blockIdx.y];
    #pragma unroll
    for (int mf = 0; mf < 4; mf++) {
        int r0 = m0 + wm0 + mf * 16 + gid;
        #pragma unroll
        for (int nf = 0; nf < 8; nf++) {
            int c = wn0 + nf * 8 + 2 * tig;
            *reinterpret_cast<float2*>(&P[(size_t)r0 * DIM + c]) =
                make_float2(acc[mf][nf][0], acc[mf][nf][1]);
            *reinterpret_cast<float2*>(&P[(size_t)(r0 + 8) * DIM + c]) =
                make_float2(acc[mf][nf][2], acc[mf][nf][3]);
        }
    }
}

// ===================== kernel 4: out = dis .* (P0 + P1 + G) + b =====================
__global__ void __launch_bounds__(256) reduce_kernel(const float* __restrict__ bias,
                                                     float* __restrict__ out) {
    int idx = blockIdx.x * 256 + threadIdx.x;     // float4 index; total NROWS*DIM/4
    int row = idx >> 5, n4 = idx & 31;
    const float4* p0 = reinterpret_cast<const float4*>(g_part[0]);
    const float4* p1 = reinterpret_cast<const float4*>(g_part[1]);
    const float4* gz = reinterpret_cast<const float4*>(g_z);
    float4 a = p0[idx], b4 = p1[idx], g = gz[idx];
    float d = g_dis[row];
    float4 bb = __ldg(reinterpret_cast<const float4*>(bias) + n4);
    float4 o;
    o.x = d * (a.x + b4.x + g.x) + bb.x;
    o.y = d * (a.y + b4.y + g.y) + bb.y;
    o.z = d * (a.z + b4.z + g.z) + bb.z;
    o.w = d * (a.w + b4.w + g.w) + bb.w;
    reinterpret_cast<float4*>(out)[idx] = o;
}

// ===================== host =====================
extern "C" void kernel_launch(void* const* d_in, const int* in_sizes, int n_in,
                              void* d_out, int out_size) {
    const float* X = (const float*)d_in[0];
    const float* A = (const float*)d_in[1];
    const float* W = (const float*)d_in[2];
    const float* b = (const float*)d_in[3];
    float* out = (float*)d_out;

    rowsum_kernel<<<NROWS, 256>>>((const float4*)A);
    z_kernel<<<NROWS / 32, 256>>>(X, W);

    static bool attr_done = false;
    if (!attr_done) {
        cudaFuncSetAttribute(gemm_kernel, cudaFuncAttributeMaxDynamicSharedMemorySize, SMEM_BYTES);
        attr_done = true;
    }
    gemm_kernel<<<dim3(NROWS / 128, 2), 128, SMEM_BYTES>>>(A);
    reduce_kernel<<<NROWS * DIM / 4 / 256, 256>>>(b, out);
}